// round 8
// baseline (speedup 1.0000x reference)
#include <cuda_runtime.h>
#include <stdint.h>
#include <math.h>

#define Bb 4
#define Ssz 2048
#define Dd 1024
#define Hh 16
#define DH 64
#define NBH (Bb*Hh)          // 64
#define BM2 128
#define BN2 64

typedef unsigned long long ull;

// Scratch (allocation-free rule: device globals)
__device__ float g_Q[NBH * Ssz * DH];   // [bh][s][d]
__device__ float g_K[NBH * Ssz * DH];   // [bh][s][d]
__device__ float g_Kmean[NBH * DH];

// packed fp32x2 FMA helpers (FFMA2 — PTX-only on sm_103a)
__device__ __forceinline__ void ffma2(ull& d, ull a, ull b) {
    asm("fma.rn.f32x2 %0, %1, %2, %0;" : "+l"(d) : "l"(a), "l"(b));
}
__device__ __forceinline__ ull bcast2(float v) {
    ull r;
    asm("mov.b64 %0, {%1, %1};" : "=l"(r) : "r"(__float_as_uint(v)));
    return r;
}
__device__ __forceinline__ float2 unpack2(ull v) {
    float2 f;
    asm("mov.b64 {%0, %1}, %2;" : "=f"(f.x), "=f"(f.y) : "l"(v));
    return f;
}

// ---------------------------------------------------------------------------
// Kernel 1: QK projection, FFMA2.  C = x @ W^T + b, de-interleaved to g_Q/g_K.
// 128x128 tile, 256 threads, 8x8 per thread packed as 4x8 f32x2 (pairs on M).
// B tile stored DUPLICATED (each value twice) so broadcast pairs load directly
// as LDS.128 — no mov.b64 packing in the inner loop.
// ---------------------------------------------------------------------------
__global__ __launch_bounds__(256, 2) void proj_kernel(const float* __restrict__ x,
                                                      const float* __restrict__ W,
                                                      const float* __restrict__ bias) {
    __shared__ float As[8][128];    // [k][m]
    __shared__ float Bs2[8][256];   // [k][2n] duplicated: Bs2[k][2c]=Bs2[k][2c+1]=B[c]
    const int m0 = blockIdx.y * 128;
    const int n0 = blockIdx.x * 128;
    const int t  = threadIdx.x;
    const int tx = t & 15, ty = t >> 4;
    const int lr = t >> 1, lk = (t & 1) * 4;

    ull acc2[4][8];
#pragma unroll
    for (int i = 0; i < 4; i++)
#pragma unroll
        for (int j = 0; j < 8; j++) acc2[i][j] = 0ull;

    const float* Ap = x + (m0 + lr) * Dd + lk;
    const float* Bp = W + (n0 + lr) * Dd + lk;

    for (int k0 = 0; k0 < Dd; k0 += 8) {
        float4 av = *(const float4*)(Ap + k0);
        float4 bv = *(const float4*)(Bp + k0);
        __syncthreads();
        As[lk + 0][lr] = av.x; As[lk + 1][lr] = av.y;
        As[lk + 2][lr] = av.z; As[lk + 3][lr] = av.w;
        *(float2*)&Bs2[lk + 0][2 * lr] = make_float2(bv.x, bv.x);
        *(float2*)&Bs2[lk + 1][2 * lr] = make_float2(bv.y, bv.y);
        *(float2*)&Bs2[lk + 2][2 * lr] = make_float2(bv.z, bv.z);
        *(float2*)&Bs2[lk + 3][2 * lr] = make_float2(bv.w, bv.w);
        __syncthreads();
#pragma unroll
        for (int k = 0; k < 8; k++) {
            ulonglong2 a01 = *(const ulonglong2*)&As[k][ty * 4];        // (m pairs 0,1)
            ulonglong2 a23 = *(const ulonglong2*)&As[k][64 + ty * 4];   // (m pairs 2,3)
            ulonglong2 b01 = *(const ulonglong2*)&Bs2[k][8 * tx];       // bcast b0,b1
            ulonglong2 b23 = *(const ulonglong2*)&Bs2[k][8 * tx + 4];   // bcast b2,b3
            ulonglong2 b45 = *(const ulonglong2*)&Bs2[k][128 + 8 * tx]; // bcast b4,b5
            ulonglong2 b67 = *(const ulonglong2*)&Bs2[k][128 + 8 * tx + 4];
            ull ap[4] = {a01.x, a01.y, a23.x, a23.y};
            ull bp[8] = {b01.x, b01.y, b23.x, b23.y, b45.x, b45.y, b67.x, b67.y};
#pragma unroll
            for (int i = 0; i < 4; i++)
#pragma unroll
                for (int j = 0; j < 8; j++)
                    ffma2(acc2[i][j], ap[i], bp[j]);
        }
    }

    // Epilogue: route column n -> (q|k)[b][h][s][d]; n = (h*64+d)*2 + c
#pragma unroll
    for (int ip = 0; ip < 4; ip++) {
        int rbase = (ip < 2) ? (ty * 4 + 2 * ip) : (64 + ty * 4 + 2 * (ip - 2));
#pragma unroll
        for (int half = 0; half < 2; half++) {
            int m = m0 + rbase + half;
            int b = m >> 11;
            int s = m & 2047;
#pragma unroll
            for (int j = 0; j < 8; j++) {
                int cc = (j < 4) ? (tx * 4 + j) : (64 + tx * 4 + (j - 4));
                int n = n0 + cc;
                float2 pr = unpack2(acc2[ip][j]);
                float v = (half == 0 ? pr.x : pr.y) + bias[n];
                int c  = n & 1;
                int hd = n >> 1;
                int h  = hd >> 6;
                int d  = hd & 63;
                int dst = ((b * Hh + h) * Ssz + s) * DH + d;
                if (c == 0) g_Q[dst] = v; else g_K[dst] = v;
            }
        }
    }
}

// ---------------------------------------------------------------------------
// Kernel 2: k_mean[bh][d] = mean over s of g_K[bh][s][d]
// ---------------------------------------------------------------------------
__global__ __launch_bounds__(256) void kmean_kernel() {
    __shared__ float red[256];
    const int bh = blockIdx.x;
    const int t = threadIdx.x;
    const int d = t & 63, part = t >> 6;
    const float* kp = g_K + bh * (Ssz * DH) + d;
    float s = 0.f;
    for (int j = part; j < Ssz; j += 4) s += kp[j * DH];
    red[t] = s;
    __syncthreads();
    if (part == 0) {
        float tot = red[d] + red[64 + d] + red[128 + d] + red[192 + d];
        g_Kmean[bh * DH + d] = tot * (1.0f / Ssz);
    }
}

__device__ __forceinline__ float selu_z(float z) {
    return z > 0.f ? 1.0507009873554805f * z
                   : 1.7580993408473766f * (expf(z) - 1.f);
}

// ---------------------------------------------------------------------------
// Kernel 3: fused attention, FFMA2 inner loops.
// Per block: one (b,h) and a 128-row i-tile. Loop j in 64-wide tiles:
//   S = Qs Ks^T ; f = selu(scale*S - mu_row) ; out += f @ V
// mu_row = scale * q_row . k_mean  (algebraic identity for the row mean)
// ---------------------------------------------------------------------------
__global__ __launch_bounds__(256) void attn_kernel(const float* __restrict__ x,
                                                   float* __restrict__ out) {
    extern __shared__ float smf[];
    float* Qs = smf;                   // [64][128]
    float* Ks = Qs + 64 * 128;         // [64][68]
    float* Vs = Ks + 64 * 68;          // [64][64]
    float* Ssm = Vs + 64 * 64;         // [64][128]
    float* mu = Ssm + 64 * 128;        // [128]
    float* km = mu + 128;              // [64]

    const int blk = blockIdx.x;
    const int bh = blk >> 4;
    const int it = blk & 15;
    const int b = bh >> 4, h = bh & 15;
    const int i0 = it * BM2;
    const int t = threadIdx.x;
    const int tx = t & 15, ty = t >> 4;

    {   // Q tile transposed: g_Q[bh][i0+r][k] -> Qs[k][r]
        const float* qg = g_Q + (bh * Ssz + i0) * DH;
#pragma unroll
        for (int p = 0; p < 8; p++) {
            int idx = p * 256 + t;
            int r = idx >> 4;
            int kq = (idx & 15) * 4;
            float4 v = *(const float4*)(qg + r * DH + kq);
            Qs[(kq + 0) * 128 + r] = v.x;
            Qs[(kq + 1) * 128 + r] = v.y;
            Qs[(kq + 2) * 128 + r] = v.z;
            Qs[(kq + 3) * 128 + r] = v.w;
        }
    }
    if (t < 64) km[t] = g_Kmean[bh * DH + t];
    __syncthreads();

    if (t < 128) {
        float s = 0.f;
#pragma unroll
        for (int k = 0; k < 64; k++) s = fmaf(Qs[k * 128 + t], km[k], s);
        mu[t] = s * 0.125f;            // scale = dh^-0.5 = 0.125
    }
    __syncthreads();

    ull oac[4][4];
#pragma unroll
    for (int i = 0; i < 4; i++)
#pragma unroll
        for (int j = 0; j < 4; j++) oac[i][j] = 0ull;

    const float* xg = x + (b * Ssz) * Dd + h * DH;
    const float* kg = g_K + bh * (Ssz * DH);

    const float4 mu0 = *(const float4*)&mu[tx * 4];
    const float4 mu1 = *(const float4*)&mu[64 + tx * 4];

    for (int j0 = 0; j0 < Ssz; j0 += BN2) {
        __syncthreads();
#pragma unroll
        for (int p = 0; p < 4; p++) {
            int idx = p * 256 + t;
            int c = idx >> 4;
            int kq = (idx & 15) * 4;
            float4 kv = *(const float4*)(kg + (j0 + c) * DH + kq);
            Ks[(kq + 0) * 68 + c] = kv.x;
            Ks[(kq + 1) * 68 + c] = kv.y;
            Ks[(kq + 2) * 68 + c] = kv.z;
            Ks[(kq + 3) * 68 + c] = kv.w;
            float4 vv = *(const float4*)(xg + (j0 + c) * Dd + kq);
            *(float4*)&Vs[c * 64 + kq] = vv;
        }
        __syncthreads();

        // S = Q K^T  (pairs along rows, FFMA2)
        ull sv[4][4];
#pragma unroll
        for (int i = 0; i < 4; i++)
#pragma unroll
            for (int j = 0; j < 4; j++) sv[i][j] = 0ull;
#pragma unroll
        for (int k = 0; k < 64; k++) {
            ulonglong2 qa = *(const ulonglong2*)&Qs[k * 128 + tx * 4];
            ulonglong2 qb = *(const ulonglong2*)&Qs[k * 128 + 64 + tx * 4];
            float4 kk = *(const float4*)&Ks[k * 68 + ty * 4];
            ull b0 = bcast2(kk.x), b1 = bcast2(kk.y);
            ull b2 = bcast2(kk.z), b3 = bcast2(kk.w);
            ffma2(sv[0][0], qa.x, b0); ffma2(sv[0][1], qa.x, b1);
            ffma2(sv[0][2], qa.x, b2); ffma2(sv[0][3], qa.x, b3);
            ffma2(sv[1][0], qa.y, b0); ffma2(sv[1][1], qa.y, b1);
            ffma2(sv[1][2], qa.y, b2); ffma2(sv[1][3], qa.y, b3);
            ffma2(sv[2][0], qb.x, b0); ffma2(sv[2][1], qb.x, b1);
            ffma2(sv[2][2], qb.x, b2); ffma2(sv[2][3], qb.x, b3);
            ffma2(sv[3][0], qb.y, b0); ffma2(sv[3][1], qb.y, b1);
            ffma2(sv[3][2], qb.y, b2); ffma2(sv[3][3], qb.y, b3);
        }
        // selu(scale*s - mu) and store S tile
#pragma unroll
        for (int j = 0; j < 4; j++) {
            int c = ty * 4 + j;
            float2 u0 = unpack2(sv[0][j]);
            float2 u1 = unpack2(sv[1][j]);
            float2 u2 = unpack2(sv[2][j]);
            float2 u3 = unpack2(sv[3][j]);
            float4 lo = make_float4(selu_z(fmaf(u0.x, 0.125f, -mu0.x)),
                                    selu_z(fmaf(u0.y, 0.125f, -mu0.y)),
                                    selu_z(fmaf(u1.x, 0.125f, -mu0.z)),
                                    selu_z(fmaf(u1.y, 0.125f, -mu0.w)));
            float4 hi = make_float4(selu_z(fmaf(u2.x, 0.125f, -mu1.x)),
                                    selu_z(fmaf(u2.y, 0.125f, -mu1.y)),
                                    selu_z(fmaf(u3.x, 0.125f, -mu1.z)),
                                    selu_z(fmaf(u3.y, 0.125f, -mu1.w)));
            *(float4*)&Ssm[c * 128 + tx * 4] = lo;
            *(float4*)&Ssm[c * 128 + 64 + tx * 4] = hi;
        }
        __syncthreads();

        // out += F V   (pairs along rows, FFMA2)
#pragma unroll
        for (int c = 0; c < 64; c++) {
            ulonglong2 sa = *(const ulonglong2*)&Ssm[c * 128 + ty * 4];
            ulonglong2 sc = *(const ulonglong2*)&Ssm[c * 128 + 64 + ty * 4];
            float4 vv = *(const float4*)&Vs[c * 64 + tx * 4];
            ull v0 = bcast2(vv.x), v1 = bcast2(vv.y);
            ull v2 = bcast2(vv.z), v3 = bcast2(vv.w);
            ffma2(oac[0][0], sa.x, v0); ffma2(oac[0][1], sa.x, v1);
            ffma2(oac[0][2], sa.x, v2); ffma2(oac[0][3], sa.x, v3);
            ffma2(oac[1][0], sa.y, v0); ffma2(oac[1][1], sa.y, v1);
            ffma2(oac[1][2], sa.y, v2); ffma2(oac[1][3], sa.y, v3);
            ffma2(oac[2][0], sc.x, v0); ffma2(oac[2][1], sc.x, v1);
            ffma2(oac[2][2], sc.x, v2); ffma2(oac[2][3], sc.x, v3);
            ffma2(oac[3][0], sc.y, v0); ffma2(oac[3][1], sc.y, v1);
            ffma2(oac[3][2], sc.y, v2); ffma2(oac[3][3], sc.y, v3);
        }
    }

    // Epilogue: out[b][i0+r][h*64 + d] = oacc * S^-0.5
    const float os = 0.022097086912079608f;   // 1/sqrt(2048)
    float* og = out + (b * Ssz + i0) * Dd + h * DH;
#pragma unroll
    for (int p = 0; p < 4; p++) {
        int rbase = (p < 2) ? (ty * 4 + 2 * p) : (64 + ty * 4 + 2 * (p - 2));
        float2 w0 = unpack2(oac[p][0]);
        float2 w1 = unpack2(oac[p][1]);
        float2 w2 = unpack2(oac[p][2]);
        float2 w3 = unpack2(oac[p][3]);
        *(float4*)(og + rbase * Dd + tx * 4) =
            make_float4(w0.x * os, w1.x * os, w2.x * os, w3.x * os);
        *(float4*)(og + (rbase + 1) * Dd + tx * 4) =
            make_float4(w0.y * os, w1.y * os, w2.y * os, w3.y * os);
    }
}

// ---------------------------------------------------------------------------
extern "C" void kernel_launch(void* const* d_in, const int* in_sizes, int n_in,
                              void* d_out, int out_size) {
    const float* x    = (const float*)d_in[0];
    const float* W    = (const float*)d_in[1];
    const float* bias = (const float*)d_in[2];
    float* out = (float*)d_out;

    const int ATTN_SMEM = (64 * 128 + 64 * 68 + 64 * 64 + 64 * 128 + 128 + 64) *
                          (int)sizeof(float);   // 100096 B
    cudaFuncSetAttribute(attn_kernel, cudaFuncAttributeMaxDynamicSharedMemorySize,
                         ATTN_SMEM);

    proj_kernel<<<dim3(16, 64), 256>>>(x, W, bias);
    kmean_kernel<<<NBH, 256>>>();
    attn_kernel<<<NBH * (Ssz / BM2), 256, ATTN_SMEM>>>(x, out);
}

// round 9
// speedup vs baseline: 1.2143x; 1.2143x over previous
#include <cuda_runtime.h>
#include <math.h>

#define Bb 4
#define Ssz 2048
#define Dd 1024
#define Hh 16
#define DH 64
#define NBH (Bb*Hh)          // 64
#define BM2 128
#define BN2 64

// Scratch (allocation-free rule: device globals)
__device__ float g_Q[NBH * Ssz * DH];   // [bh][s][d]
__device__ float g_K[NBH * Ssz * DH];   // [bh][s][d]
__device__ float g_Kmean[NBH * DH];

// ---------------------------------------------------------------------------
// Kernel 1: fused QK projection  C = x @ W^T + b, de-interleaved into g_Q/g_K
// 128x128 tile, 8x8 microtile, software-pipelined global->smem staging.
// ---------------------------------------------------------------------------
__global__ __launch_bounds__(256, 2) void proj_kernel(const float* __restrict__ x,
                                                      const float* __restrict__ W,
                                                      const float* __restrict__ bias) {
    __shared__ float As[8][128];   // [k][m]
    __shared__ float Bs[8][128];   // [k][n]
    const int m0 = blockIdx.y * 128;
    const int n0 = blockIdx.x * 128;
    const int t  = threadIdx.x;
    const int tx = t & 15, ty = t >> 4;
    const int lr = t >> 1, lk = (t & 1) * 4;

    float acc[8][8];
#pragma unroll
    for (int i = 0; i < 8; i++)
#pragma unroll
        for (int j = 0; j < 8; j++) acc[i][j] = 0.f;

    const float* Ap = x + (m0 + lr) * Dd + lk;
    const float* Bp = W + (n0 + lr) * Dd + lk;

    // prologue: prefetch chunk 0
    float4 av = *(const float4*)(Ap);
    float4 bv = *(const float4*)(Bp);

    for (int k0 = 0; k0 < Dd; k0 += 8) {
        __syncthreads();
        As[lk + 0][lr] = av.x; As[lk + 1][lr] = av.y;
        As[lk + 2][lr] = av.z; As[lk + 3][lr] = av.w;
        Bs[lk + 0][lr] = bv.x; Bs[lk + 1][lr] = bv.y;
        Bs[lk + 2][lr] = bv.z; Bs[lk + 3][lr] = bv.w;
        __syncthreads();
        // issue next chunk's loads NOW — they overlap the compute below
        int kn = (k0 + 8 < Dd) ? k0 + 8 : 0;
        av = *(const float4*)(Ap + kn);
        bv = *(const float4*)(Bp + kn);
#pragma unroll
        for (int k = 0; k < 8; k++) {
            float a[8], bb[8];
            float4 a0 = *(const float4*)&As[k][ty * 4];
            float4 a1 = *(const float4*)&As[k][64 + ty * 4];
            float4 b0 = *(const float4*)&Bs[k][tx * 4];
            float4 b1 = *(const float4*)&Bs[k][64 + tx * 4];
            a[0]=a0.x; a[1]=a0.y; a[2]=a0.z; a[3]=a0.w;
            a[4]=a1.x; a[5]=a1.y; a[6]=a1.z; a[7]=a1.w;
            bb[0]=b0.x; bb[1]=b0.y; bb[2]=b0.z; bb[3]=b0.w;
            bb[4]=b1.x; bb[5]=b1.y; bb[6]=b1.z; bb[7]=b1.w;
#pragma unroll
            for (int i = 0; i < 8; i++)
#pragma unroll
                for (int j = 0; j < 8; j++)
                    acc[i][j] = fmaf(a[i], bb[j], acc[i][j]);
        }
    }

    // Epilogue: route column n -> (q|k)[b][h][s][d]; n = (h*64+d)*2 + c
#pragma unroll
    for (int i = 0; i < 8; i++) {
        int rr = (i < 4) ? (ty * 4 + i) : (64 + ty * 4 + (i - 4));
        int m = m0 + rr;
        int b = m >> 11;
        int s = m & 2047;
#pragma unroll
        for (int j = 0; j < 8; j++) {
            int cc = (j < 4) ? (tx * 4 + j) : (64 + tx * 4 + (j - 4));
            int n = n0 + cc;
            float v = acc[i][j] + bias[n];
            int c  = n & 1;
            int hd = n >> 1;            // h*64 + d
            int h  = hd >> 6;
            int d  = hd & 63;
            int dst = ((b * Hh + h) * Ssz + s) * DH + d;
            if (c == 0) g_Q[dst] = v; else g_K[dst] = v;
        }
    }
}

// ---------------------------------------------------------------------------
// Kernel 2: k_mean[bh][d] = mean over s of g_K[bh][s][d]
// ---------------------------------------------------------------------------
__global__ __launch_bounds__(256) void kmean_kernel() {
    __shared__ float red[256];
    const int bh = blockIdx.x;
    const int t = threadIdx.x;
    const int d = t & 63, part = t >> 6;
    const float* kp = g_K + bh * (Ssz * DH) + d;
    float s = 0.f;
    for (int j = part; j < Ssz; j += 4) s += kp[j * DH];
    red[t] = s;
    __syncthreads();
    if (part == 0) {
        float tot = red[d] + red[64 + d] + red[128 + d] + red[192 + d];
        g_Kmean[bh * DH + d] = tot * (1.0f / Ssz);
    }
}

// selu(z) with fast exp (MUFU.EX2): error ~1e-7 rel, fine vs 1e-3 gate
__device__ __forceinline__ float selu_z(float z) {
    const float lam = 1.0507009873554805f;
    const float lam_al = 1.7580993408473766f;
    float e = __expf(z);
    return z > 0.f ? lam * z : fmaf(lam_al, e, -lam_al);
}

// ---------------------------------------------------------------------------
// Kernel 3: fused attention.
// Per block: one (b,h) and a 128-row i-tile. Loop j in 64-wide tiles:
//   S = Qs Ks^T ; f = selu(scale*S - mu_row) ; out += f @ V
// mu_row = scale * q_row . k_mean  (algebraic identity for the row mean)
// Next K/V tile prefetched into registers during GEMM2.
// ---------------------------------------------------------------------------
__global__ __launch_bounds__(256) void attn_kernel(const float* __restrict__ x,
                                                   float* __restrict__ out) {
    extern __shared__ float sm[];
    float* Qs = sm;                    // [64][128]   Qs[k*128 + r]
    float* Ks = Qs + 64 * 128;         // [64][68]    Ks[k*68 + c]
    float* Vs = Ks + 64 * 68;          // [64][64]    Vs[c*64 + d]
    float* Ssm = Vs + 64 * 64;         // [64][128]   Ssm[c*128 + r]
    float* mu = Ssm + 64 * 128;        // [128]
    float* km = mu + 128;              // [64]

    const int blk = blockIdx.x;
    const int bh = blk >> 4;           // 0..63
    const int it = blk & 15;
    const int b = bh >> 4, h = bh & 15;
    const int i0 = it * BM2;
    const int t = threadIdx.x;
    const int tx = t & 15, ty = t >> 4;

    // Load Q tile transposed: g_Q[bh][i0+r][k] -> Qs[k][r]
    {
        const float* qg = g_Q + (bh * Ssz + i0) * DH;
#pragma unroll
        for (int p = 0; p < 8; p++) {
            int idx = p * 256 + t;          // float4 index 0..2047
            int r = idx >> 4;               // 0..127
            int kq = (idx & 15) * 4;        // 0..60
            float4 v = *(const float4*)(qg + r * DH + kq);
            Qs[(kq + 0) * 128 + r] = v.x;
            Qs[(kq + 1) * 128 + r] = v.y;
            Qs[(kq + 2) * 128 + r] = v.z;
            Qs[(kq + 3) * 128 + r] = v.w;
        }
    }
    if (t < 64) km[t] = g_Kmean[bh * DH + t];
    __syncthreads();

    if (t < 128) {
        float s = 0.f;
#pragma unroll
        for (int k = 0; k < 64; k++) s = fmaf(Qs[k * 128 + t], km[k], s);
        mu[t] = s * 0.125f;                // scale = dh^-0.5 = 0.125
    }
    __syncthreads();

    float oacc[8][4];
#pragma unroll
    for (int i = 0; i < 8; i++)
#pragma unroll
        for (int j = 0; j < 4; j++) oacc[i][j] = 0.f;

    const float* xg = x + (b * Ssz) * Dd + h * DH;    // V[j][d] = xg[j*Dd + d]
    const float* kg = g_K + bh * (Ssz * DH);

    // per-thread tile-load mapping (4 float4 each for K and V)
    const int lc  = t >> 4;              // 0..15  -> c = p*16? no: see below
    // mapping: idx = p*256 + t ; c = idx>>4 ; kq = (idx&15)*4
    float4 pk[4], pv[4];
#pragma unroll
    for (int p = 0; p < 4; p++) {
        int idx = p * 256 + t;
        int c = idx >> 4;
        int kq = (idx & 15) * 4;
        pk[p] = *(const float4*)(kg + c * DH + kq);
        pv[p] = *(const float4*)(xg + c * Dd + kq);
    }
    (void)lc;

    for (int j0 = 0; j0 < Ssz; j0 += BN2) {
        __syncthreads();   // WAR: previous iter's GEMM2 readers done
        // Store prefetched K (transposed) and V tiles
#pragma unroll
        for (int p = 0; p < 4; p++) {
            int idx = p * 256 + t;
            int c = idx >> 4;
            int kq = (idx & 15) * 4;
            Ks[(kq + 0) * 68 + c] = pk[p].x;
            Ks[(kq + 1) * 68 + c] = pk[p].y;
            Ks[(kq + 2) * 68 + c] = pk[p].z;
            Ks[(kq + 3) * 68 + c] = pk[p].w;
            *(float4*)&Vs[c * 64 + kq] = pv[p];
        }
        __syncthreads();

        // S-compute: thread owns rows {tx*4+i, 64+tx*4+i}, cols {ty*4+j}
        float sv[8][4];
#pragma unroll
        for (int i = 0; i < 8; i++)
#pragma unroll
            for (int j = 0; j < 4; j++) sv[i][j] = 0.f;
#pragma unroll
        for (int k = 0; k < 64; k++) {
            float4 q0 = *(const float4*)&Qs[k * 128 + tx * 4];
            float4 q1 = *(const float4*)&Qs[k * 128 + 64 + tx * 4];
            float4 kk = *(const float4*)&Ks[k * 68 + ty * 4];
            float qa[8] = {q0.x, q0.y, q0.z, q0.w, q1.x, q1.y, q1.z, q1.w};
            float kb[4] = {kk.x, kk.y, kk.z, kk.w};
#pragma unroll
            for (int i = 0; i < 8; i++)
#pragma unroll
                for (int j = 0; j < 4; j++)
                    sv[i][j] = fmaf(qa[i], kb[j], sv[i][j]);
        }
        // selu(scale*s - mu)
#pragma unroll
        for (int i = 0; i < 8; i++) {
            int r = (i < 4) ? (tx * 4 + i) : (64 + tx * 4 + (i - 4));
            float m_ = mu[r];
#pragma unroll
            for (int j = 0; j < 4; j++) {
                float z = fmaf(sv[i][j], 0.125f, -m_);
                sv[i][j] = selu_z(z);
            }
        }
        // Write S tile
#pragma unroll
        for (int j = 0; j < 4; j++) {
            int c = ty * 4 + j;
            *(float4*)&Ssm[c * 128 + tx * 4] =
                make_float4(sv[0][j], sv[1][j], sv[2][j], sv[3][j]);
            *(float4*)&Ssm[c * 128 + 64 + tx * 4] =
                make_float4(sv[4][j], sv[5][j], sv[6][j], sv[7][j]);
        }

        // Prefetch next tile's K/V into registers (sv is dead now);
        // these LDGs overlap the Ssm sync + GEMM2 below.
        {
            int jn = (j0 + BN2 < Ssz) ? j0 + BN2 : 0;
            const float* kgn = kg + jn * DH;
            const float* xgn = xg + jn * Dd;
#pragma unroll
            for (int p = 0; p < 4; p++) {
                int idx = p * 256 + t;
                int c = idx >> 4;
                int kq = (idx & 15) * 4;
                pk[p] = *(const float4*)(kgn + c * DH + kq);
                pv[p] = *(const float4*)(xgn + c * Dd + kq);
            }
        }
        __syncthreads();

        // GEMM2: out[r][d] += S[r][c] * V[c][d]; rows {ty*4+i, 64+ty*4+i}, d {tx*4+j}
#pragma unroll
        for (int c = 0; c < 64; c++) {
            float4 s0 = *(const float4*)&Ssm[c * 128 + ty * 4];
            float4 s1 = *(const float4*)&Ssm[c * 128 + 64 + ty * 4];
            float4 vv = *(const float4*)&Vs[c * 64 + tx * 4];
            float sa[8] = {s0.x, s0.y, s0.z, s0.w, s1.x, s1.y, s1.z, s1.w};
            float vb[4] = {vv.x, vv.y, vv.z, vv.w};
#pragma unroll
            for (int i = 0; i < 8; i++)
#pragma unroll
                for (int j = 0; j < 4; j++)
                    oacc[i][j] = fmaf(sa[i], vb[j], oacc[i][j]);
        }
    }

    // Epilogue: out[b][i0+r][h*64 + d] = oacc * S^-0.5
    const float os = 0.022097086912079608f;   // 1/sqrt(2048)
    float* og = out + (b * Ssz + i0) * Dd + h * DH;
#pragma unroll
    for (int i = 0; i < 8; i++) {
        int r = (i < 4) ? (ty * 4 + i) : (64 + ty * 4 + (i - 4));
        float4 v = make_float4(oacc[i][0] * os, oacc[i][1] * os,
                               oacc[i][2] * os, oacc[i][3] * os);
        *(float4*)(og + r * Dd + tx * 4) = v;
    }
}

// ---------------------------------------------------------------------------
extern "C" void kernel_launch(void* const* d_in, const int* in_sizes, int n_in,
                              void* d_out, int out_size) {
    const float* x    = (const float*)d_in[0];
    const float* W    = (const float*)d_in[1];
    const float* bias = (const float*)d_in[2];
    float* out = (float*)d_out;

    const int ATTN_SMEM = (64 * 128 + 64 * 68 + 64 * 64 + 64 * 128 + 128 + 64) *
                          (int)sizeof(float);   // 100096 B
    cudaFuncSetAttribute(attn_kernel, cudaFuncAttributeMaxDynamicSharedMemorySize,
                         ATTN_SMEM);

    proj_kernel<<<dim3(16, 64), 256>>>(x, W, bias);
    kmean_kernel<<<NBH, 256>>>();
    attn_kernel<<<NBH * (Ssz / BM2), 256, ATTN_SMEM>>>(x, out);
}